// round 14
// baseline (speedup 1.0000x reference)
#include <cuda_runtime.h>

#define NBLK 128
#define NTHR 512

#define BB   32
#define TT   128
#define DD   16
#define HH   256
#define OSZ  8
#define NWIN 120
#define NSTEPS 127
#define TRAJ_BS (TT*DD)     /* 2048 */
#define OUT_BS  (NWIN*OSZ)  /* 960  */
#define HN_OFF  30720
#define CN_OFF  47104

typedef unsigned long long ull;

// -------- persistent device state (no allocations allowed) --------
__device__ float gH0[2][8][BB][HH];   // [parity][slot][b][u] layer-0 hidden, ping-pong
__device__ float gH1[2][8][BB][HH];   // layer-1 hidden
__device__ unsigned g_barc = 0;       // final global barrier
__device__ volatile unsigned g_barg = 0;
__device__ unsigned g_gc[8];          // per-group barrier counters
__device__ volatile unsigned g_gg[8]; // per-group generations (monotonic across replays)
__device__ unsigned g_outcnt[NWIN];   // per-window completion counters (reset at kernel end)

// -------- helpers --------
__device__ __forceinline__ ull pack2(float x, float y) {
    ull r; asm("mov.b64 %0, {%1, %2};" : "=l"(r) : "f"(x), "f"(y)); return r;
}
__device__ __forceinline__ float2 unpack2(ull v) {
    float2 r; asm("mov.b64 {%0, %1}, %2;" : "=f"(r.x), "=f"(r.y) : "l"(v)); return r;
}
__device__ __forceinline__ void fma2(ull& d, ull a, ull b) {
    asm("fma.rn.f32x2 %0, %1, %2, %0;" : "+l"(d) : "l"(a), "l"(b));
}
__device__ __forceinline__ float sum2(ull v) { float2 f = unpack2(v); return f.x + f.y; }

// fast sigmoid / tanh: __expf (MUFU.EX2) + __fdividef (MUFU.RCP); rel err ~1e-6
__device__ __forceinline__ float sigf(float x) {
    float e = __expf(-x);
    return __fdividef(1.0f, 1.0f + e);
}
__device__ __forceinline__ float tanhfast(float x) {
    float e = __expf(2.0f * x);
    return 1.0f - __fdividef(2.0f, e + 1.0f);
}

// 16-CTA group barrier (only CTAs sharing wg exchange h-state)
__device__ __forceinline__ void group_bar(int wg) {
    __threadfence();            // drain this CTA's global stores to L2
    __syncthreads();
    if (threadIdx.x == 0) {
        unsigned old = g_gg[wg];
        if (atomicAdd(&g_gc[wg], 1u) == 15u) {
            atomicExch(&g_gc[wg], 0u);
            __threadfence();
            g_gg[wg] = old + 1u;
        } else {
            while (g_gg[wg] == old) { }
            __threadfence();
        }
    }
    __syncthreads();
}

// final global barrier (used once, for replay-safe counter reset)
__device__ __forceinline__ void grid_bar_global() {
    __threadfence();
    __syncthreads();
    if (threadIdx.x == 0) {
        unsigned old = g_barg;
        if (atomicAdd(&g_barc, 1u) == NBLK - 1) {
            atomicExch(&g_barc, 0u);
            __threadfence();
            g_barg = old + 1u;
        } else {
            while (g_barg == old) __nanosleep(32);
            __threadfence();
        }
    }
    __syncthreads();
}

// ---- quarter-chunk GEMM (K=32 of a staged 128-chunk). sH: [32][128] row-major.
// sW chunk layout: 64 k2-rows x 128 fl; row r covers k-pair (2r,2r+1);
// within row: (g>>1)*64 + ul*4 + (g&1)*2 holds the f32x2 for (g,u) over that pair.
__device__ __forceinline__ void gemm32(ull acc[4][4],
                                       const float* __restrict__ sH,
                                       const float* __restrict__ sW,
                                       int ul, int b0, int kh)
{
    const float* hp = sH + b0 * 128 + kh * 32;
    const float* wp = sW + kh * 2048 + ul * 4;
#pragma unroll
    for (int q = 0; q < 8; ++q) {
        ulonglong2 h0 = *(const ulonglong2*)(hp + 0 * 128 + q * 4);
        ulonglong2 h1 = *(const ulonglong2*)(hp + 1 * 128 + q * 4);
        ulonglong2 h2 = *(const ulonglong2*)(hp + 2 * 128 + q * 4);
        ulonglong2 h3 = *(const ulonglong2*)(hp + 3 * 128 + q * 4);
        {
            const float* w = wp + (2 * q) * 128;
            ulonglong2 wA = *(const ulonglong2*)(w);
            ulonglong2 wB = *(const ulonglong2*)(w + 64);
            fma2(acc[0][0], h0.x, wA.x); fma2(acc[0][1], h1.x, wA.x);
            fma2(acc[0][2], h2.x, wA.x); fma2(acc[0][3], h3.x, wA.x);
            fma2(acc[1][0], h0.x, wA.y); fma2(acc[1][1], h1.x, wA.y);
            fma2(acc[1][2], h2.x, wA.y); fma2(acc[1][3], h3.x, wA.y);
            fma2(acc[2][0], h0.x, wB.x); fma2(acc[2][1], h1.x, wB.x);
            fma2(acc[2][2], h2.x, wB.x); fma2(acc[2][3], h3.x, wB.x);
            fma2(acc[3][0], h0.x, wB.y); fma2(acc[3][1], h1.x, wB.y);
            fma2(acc[3][2], h2.x, wB.y); fma2(acc[3][3], h3.x, wB.y);
        }
        {
            const float* w = wp + (2 * q + 1) * 128;
            ulonglong2 wA = *(const ulonglong2*)(w);
            ulonglong2 wB = *(const ulonglong2*)(w + 64);
            fma2(acc[0][0], h0.y, wA.x); fma2(acc[0][1], h1.y, wA.x);
            fma2(acc[0][2], h2.y, wA.x); fma2(acc[0][3], h3.y, wA.x);
            fma2(acc[1][0], h0.y, wA.y); fma2(acc[1][1], h1.y, wA.y);
            fma2(acc[1][2], h2.y, wA.y); fma2(acc[1][3], h3.y, wA.y);
            fma2(acc[2][0], h0.y, wB.x); fma2(acc[2][1], h1.y, wB.x);
            fma2(acc[2][2], h2.y, wB.x); fma2(acc[2][3], h3.y, wB.x);
            fma2(acc[3][0], h0.y, wB.y); fma2(acc[3][1], h1.y, wB.y);
            fma2(acc[3][2], h2.y, wB.y); fma2(acc[3][3], h3.y, wB.y);
        }
    }
}

// K=4 slice of x-part GEMM over sX [32][16]; each kh group does q = kh.
__device__ __forceinline__ void gemm4(ull acc[4][4],
                                      const float* __restrict__ sX,
                                      const float* __restrict__ sW,
                                      int ul, int b0, int q)
{
    const float* hp = sX + b0 * 16;
    const float* wp = sW + ul * 4;
    ulonglong2 h0 = *(const ulonglong2*)(hp + 0 * 16 + q * 4);
    ulonglong2 h1 = *(const ulonglong2*)(hp + 1 * 16 + q * 4);
    ulonglong2 h2 = *(const ulonglong2*)(hp + 2 * 16 + q * 4);
    ulonglong2 h3 = *(const ulonglong2*)(hp + 3 * 16 + q * 4);
#pragma unroll
    for (int e = 0; e < 2; ++e) {
        const float* w = wp + (2 * q + e) * 128;
        ulonglong2 wA = *(const ulonglong2*)(w);
        ulonglong2 wB = *(const ulonglong2*)(w + 64);
        ull v0 = e ? h0.y : h0.x, v1 = e ? h1.y : h1.x;
        ull v2 = e ? h2.y : h2.x, v3 = e ? h3.y : h3.x;
        fma2(acc[0][0], v0, wA.x); fma2(acc[0][1], v1, wA.x);
        fma2(acc[0][2], v2, wA.x); fma2(acc[0][3], v3, wA.x);
        fma2(acc[1][0], v0, wA.y); fma2(acc[1][1], v1, wA.y);
        fma2(acc[1][2], v2, wA.y); fma2(acc[1][3], v3, wA.y);
        fma2(acc[2][0], v0, wB.x); fma2(acc[2][1], v1, wB.x);
        fma2(acc[2][2], v2, wB.x); fma2(acc[2][3], v3, wB.x);
        fma2(acc[3][0], v0, wB.y); fma2(acc[3][1], v1, wB.y);
        fma2(acc[3][2], v2, wB.y); fma2(acc[3][3], v3, wB.y);
    }
}

__device__ __forceinline__ void ldg_chunk(float4 r[2], const float* __restrict__ src, int tid) {
#pragma unroll
    for (int j = 0; j < 2; ++j) {
        int idx = tid + j * NTHR;
        int b = idx >> 5, q = idx & 31;
        r[j] = __ldcg((const float4*)(src + b * HH) + q);
    }
}
__device__ __forceinline__ void sts_chunk(const float4 r[2], float* __restrict__ sH, int tid) {
#pragma unroll
    for (int j = 0; j < 2; ++j) {
        int idx = tid + j * NTHR;
        *(float4*)(sH + idx * 4) = r[j];
    }
}

__device__ __forceinline__ void stage_w256(const float* __restrict__ src,
                                           float* __restrict__ dst,
                                           int ubase, int tid)
{
    for (int i = tid; i < 8192; i += NTHR) {
        int r = i >> 7, k2 = i & 127;
        int uu = r >> 2, g = r & 3;
        int grow = g * 256 + ubase + uu;
        float2 w = __ldg((const float2*)(src + grow * 256 + 2 * k2));
        int doff = k2 * 128 + (g >> 1) * 64 + uu * 4 + (g & 1) * 2;
        dst[doff] = w.x; dst[doff + 1] = w.y;
    }
}

// fold slot: partial of (gate g, batch-in-quad j) from source kh', lane t128
#define FOLD(g, j, m) (((((g) * 4 + (j)) * 3) + (m)) * 128)

__global__ void __launch_bounds__(NTHR, 1)
orlstm_kernel(const float* __restrict__ traj,
              const float* __restrict__ Wih0, const float* __restrict__ Whh0,
              const float* __restrict__ bih0, const float* __restrict__ bhh0,
              const float* __restrict__ Wih1, const float* __restrict__ Whh1,
              const float* __restrict__ bih1, const float* __restrict__ bhh1,
              const float* __restrict__ Wlin, const float* __restrict__ blin,
              float* __restrict__ outp)
{
    extern __shared__ float smem[];
    float* sWhh0 = smem;                    // 16384 fl
    float* sWih1 = sWhh0 + 16384;
    float* sWhh1 = sWih1 + 16384;
    float* sWih0 = sWhh1 + 16384;           // 1024 fl
    float* sB0   = sWih0 + 1024;            // 64
    float* sB1   = sB0 + 64;                // 64
    float* sX    = sB1 + 64;                // 512
    float* sR    = sX + 512;                // 6144 fl: chunk staging (first 4096) + fold buffer
    // total 56960 floats = 227840 B

    const int tid   = threadIdx.x;
    const int us    = blockIdx.x & 15;      // unit-slice 0..15
    const int wg    = blockIdx.x >> 4;      // window slot 0..7
    const int ubase = us * 16;
    const int ul    = tid & 15;
    const int bq    = (tid >> 4) & 7;
    const int kh    = tid >> 7;             // k-quarter / batch-in-quad owner
    const int t128  = tid & 127;
    const int b0    = bq * 4;
    const int bown  = b0 + kh;              // the one batch this thread's cell update owns
    const int u     = ubase + ul;

    // ---- one-time weight staging ----
    stage_w256(Whh0, sWhh0, ubase, tid);
    stage_w256(Wih1, sWih1, ubase, tid);
    stage_w256(Whh1, sWhh1, ubase, tid);
    for (int i = tid; i < 512; i += NTHR) {
        int r = i >> 3, k2 = i & 7;
        int uu = r >> 2, g = r & 3;
        int grow = g * 256 + ubase + uu;
        float2 w = __ldg((const float2*)(Wih0 + grow * 16 + 2 * k2));
        int doff = k2 * 128 + (g >> 1) * 64 + uu * 4 + (g & 1) * 2;
        sWih0[doff] = w.x; sWih0[doff + 1] = w.y;
    }
    if (tid < 64) {
        int uu = tid >> 2, g = tid & 3;
        int grow = g * 256 + ubase + uu;
        sB0[uu * 4 + g] = __ldg(bih0 + grow) + __ldg(bhh0 + grow);
        sB1[uu * 4 + g] = __ldg(bih1 + grow) + __ldg(bhh1 + grow);
    }
    __syncthreads();

    float c0 = 0.f, c1 = 0.f;   // cell state for batch bown (this thread)

    volatile unsigned* vcnt = (volatile unsigned*)g_outcnt;

    for (int k = 0; k < NSTEPS; ++k) {
        const int p = k & 1;
        const int s = (k - wg + 8) & 7;
        const int t = k - s;
        const bool active = (t >= 0) && (t < NWIN);

        ull acc[4][4];
        float hn1;

        // ---------------- PHASE A: layer-0 cell ----------------
        if (active) {
            if (s == 0 && us == 0 && tid < 256) {
                int b = tid >> 3, o = tid & 7;
                __stcg(outp + b * OUT_BS + t * OSZ + o, 0.f);
            }
            {
                int jj = t + s - 8;
                if (t >= 1 && jj >= 0 && tid == 0) {
                    while (vcnt[jj] < 16u) { }
                    __threadfence();
                }
            }
            __syncthreads();

            // build x input [32][16]
            {
                int b = tid >> 4, col = tid & 15;
                float v;
                if (col < 8) {
                    int idx = (t >= 1 && t <= 7 && s >= 8 - t) ? (2 * t + s - 1) : (t + s);
                    v = __ldg(traj + b * TRAJ_BS + idx * DD + col);
                } else {
                    int j = t + s - 8;
                    if (t >= 1 && j >= 0)
                        v = __ldcg(outp + b * OUT_BS + j * OSZ + (col - 8));
                    else
                        v = __ldg(traj + b * TRAJ_BS + (t + s) * DD + col);
                }
                if (tid < 512) sX[tid] = v;
            }
            __syncthreads();

            // init: kh0 carries bias; all kh do one K=4 slice of the x-part
            if (kh == 0) {
#pragma unroll
                for (int g = 0; g < 4; ++g) {
                    ull bz = pack2(sB0[ul * 4 + g], 0.f);
#pragma unroll
                    for (int j = 0; j < 4; ++j) acc[g][j] = bz;
                }
            } else {
#pragma unroll
                for (int g = 0; g < 4; ++g)
#pragma unroll
                    for (int j = 0; j < 4; ++j) acc[g][j] = 0ull;
            }
            gemm4(acc, sX, sWih0, ul, b0, kh);

            if (s > 0) {
                const float* src = &gH0[p][wg][0][0];
                float4 r[2];
                ldg_chunk(r, src, tid);
#pragma unroll
                for (int c = 0; c < 2; ++c) {
                    __syncthreads();
                    sts_chunk(r, sR, tid);
                    __syncthreads();
                    if (c == 0) ldg_chunk(r, src + 128, tid);
                    gemm32(acc, sR, sWhh0 + c * 8192, ul, b0, kh);
                }
            }

            // fold: each thread gives away partials for j != kh
            __syncthreads();
#pragma unroll
            for (int g = 0; g < 4; ++g)
#pragma unroll
                for (int j = 0; j < 4; ++j)
                    if (j != kh) {
                        int m = kh - (kh > j ? 1 : 0);
                        sR[FOLD(g, j, m) + t128] = sum2(acc[g][j]);
                    }
            __syncthreads();

            // distributed cell update: one batch per thread
            {
                float gi = sum2(acc[0][kh]) + sR[FOLD(0, kh, 0) + t128] + sR[FOLD(0, kh, 1) + t128] + sR[FOLD(0, kh, 2) + t128];
                float gf = sum2(acc[1][kh]) + sR[FOLD(1, kh, 0) + t128] + sR[FOLD(1, kh, 1) + t128] + sR[FOLD(1, kh, 2) + t128];
                float gG = sum2(acc[2][kh]) + sR[FOLD(2, kh, 0) + t128] + sR[FOLD(2, kh, 1) + t128] + sR[FOLD(2, kh, 2) + t128];
                float gO = sum2(acc[3][kh]) + sR[FOLD(3, kh, 0) + t128] + sR[FOLD(3, kh, 1) + t128] + sR[FOLD(3, kh, 2) + t128];
                float cn = (s ? sigf(gf) * c0 : 0.f) + sigf(gi) * tanhfast(gG);
                c0 = cn;
                float hn = sigf(gO) * tanhfast(cn);
                __stcg(&gH0[p ^ 1][wg][bown][u], hn);
                if (t == NWIN - 1 && s == 7) {
                    outp[HN_OFF + bown * HH + u] = hn;
                    outp[CN_OFF + bown * HH + u] = cn;
                }
            }
        }
        group_bar(wg);

        // ---------------- PHASE B: layer-1 cell (+ pred for finishing window) ----
        if (active) {
            if (kh == 0) {
#pragma unroll
                for (int g = 0; g < 4; ++g) {
                    ull bz = pack2(sB1[ul * 4 + g], 0.f);
#pragma unroll
                    for (int j = 0; j < 4; ++j) acc[g][j] = bz;
                }
            } else {
#pragma unroll
                for (int g = 0; g < 4; ++g)
#pragma unroll
                    for (int j = 0; j < 4; ++j) acc[g][j] = 0ull;
            }
            const float* srcA = &gH0[p ^ 1][wg][0][0];
            const float* srcB = &gH1[p][wg][0][0];
            const int nch = (s > 0) ? 4 : 2;
            float4 r[2];
            ldg_chunk(r, srcA, tid);
            for (int c = 0; c < nch; ++c) {
                __syncthreads();
                sts_chunk(r, sR, tid);
                __syncthreads();
                if (c + 1 < nch) {
                    const float* nsrc = (c + 1 < 2) ? (srcA + (c + 1) * 128)
                                                    : (srcB + (c - 1) * 128);
                    ldg_chunk(r, nsrc, tid);
                }
                const float* wb = (c < 2) ? (sWih1 + c * 8192)
                                          : (sWhh1 + (c - 2) * 8192);
                gemm32(acc, sR, wb, ul, b0, kh);
            }

            // fold
            __syncthreads();
#pragma unroll
            for (int g = 0; g < 4; ++g)
#pragma unroll
                for (int j = 0; j < 4; ++j)
                    if (j != kh) {
                        int m = kh - (kh > j ? 1 : 0);
                        sR[FOLD(g, j, m) + t128] = sum2(acc[g][j]);
                    }
            __syncthreads();

            // distributed cell update
            {
                float gi = sum2(acc[0][kh]) + sR[FOLD(0, kh, 0) + t128] + sR[FOLD(0, kh, 1) + t128] + sR[FOLD(0, kh, 2) + t128];
                float gf = sum2(acc[1][kh]) + sR[FOLD(1, kh, 0) + t128] + sR[FOLD(1, kh, 1) + t128] + sR[FOLD(1, kh, 2) + t128];
                float gG = sum2(acc[2][kh]) + sR[FOLD(2, kh, 0) + t128] + sR[FOLD(2, kh, 1) + t128] + sR[FOLD(2, kh, 2) + t128];
                float gO = sum2(acc[3][kh]) + sR[FOLD(3, kh, 0) + t128] + sR[FOLD(3, kh, 1) + t128] + sR[FOLD(3, kh, 2) + t128];
                float cn = (s ? sigf(gf) * c1 : 0.f) + sigf(gi) * tanhfast(gG);
                c1 = cn;
                float hn = sigf(gO) * tanhfast(cn);
                hn1 = hn;
                __stcg(&gH1[p ^ 1][wg][bown][u], hn);
                if (t == NWIN - 1 && s == 7) {
                    outp[HN_OFF + BB * HH + bown * HH + u] = hn;
                    outp[CN_OFF + BB * HH + bown * HH + u] = cn;
                }
            }

            // finishing window: pred = h1T @ Wlin.T, all warps participate
            if (s == 7) {
#pragma unroll
                for (int o = 0; o < 8; ++o) {
                    float v = hn1 * __ldg(Wlin + o * HH + u);
                    v += __shfl_xor_sync(0xffffffffu, v, 1);
                    v += __shfl_xor_sync(0xffffffffu, v, 2);
                    v += __shfl_xor_sync(0xffffffffu, v, 4);
                    v += __shfl_xor_sync(0xffffffffu, v, 8);
                    if (ul == 0)
                        atomicAdd(outp + bown * OUT_BS + t * OSZ + o, v);
                }
                // us==0 CTA adds the base (out[t-1] + b_lin)
                if (us == 0 && tid < 256) {
                    int b = tid >> 3, o = tid & 7;
                    float base;
                    if (t == 0) {
                        base = __ldg(traj + b * TRAJ_BS + 7 * DD + OSZ + o);
                    } else {
                        while (vcnt[t - 1] < 16u) { }
                        __threadfence();
                        base = __ldcg(outp + b * OUT_BS + (t - 1) * OSZ + o);
                    }
                    atomicAdd(outp + b * OUT_BS + t * OSZ + o, base + __ldg(blin + o));
                }
                __syncthreads();
                if (tid == 0) {
                    __threadfence();
                    atomicAdd(&g_outcnt[t], 1u);   // release: this CTA's contributions done
                }
            }
        }
        group_bar(wg);
    }

    // replay-safe reset of per-window counters
    grid_bar_global();
    if (blockIdx.x == 0) {
        for (int i = tid; i < NWIN; i += NTHR) g_outcnt[i] = 0u;
    }
}

extern "C" void kernel_launch(void* const* d_in, const int* in_sizes, int n_in,
                              void* d_out, int out_size)
{
    (void)in_sizes; (void)n_in; (void)out_size;
    const size_t smem_bytes = 56960 * sizeof(float);  // 227840 B
    cudaFuncSetAttribute(orlstm_kernel,
                         cudaFuncAttributeMaxDynamicSharedMemorySize,
                         (int)smem_bytes);
    orlstm_kernel<<<NBLK, NTHR, smem_bytes>>>(
        (const float*)d_in[0],
        (const float*)d_in[1], (const float*)d_in[2],
        (const float*)d_in[3], (const float*)d_in[4],
        (const float*)d_in[5], (const float*)d_in[6],
        (const float*)d_in[7], (const float*)d_in[8],
        (const float*)d_in[9], (const float*)d_in[10],
        (float*)d_out);
}

// round 16
// speedup vs baseline: 1.0953x; 1.0953x over previous
#include <cuda_runtime.h>

#define NBLK 128
#define NTHR 512

#define BB   32
#define TT   128
#define DD   16
#define HH   256
#define OSZ  8
#define NWIN 120
#define NSTEPS 128           /* layer-skewed: one extra phase */
#define TRAJ_BS (TT*DD)     /* 2048 */
#define OUT_BS  (NWIN*OSZ)  /* 960  */
#define HN_OFF  30720
#define CN_OFF  47104
#define SPIN_MAX (1u<<22)   /* bounded spin: converts would-be deadlock into wrong answer */

typedef unsigned long long ull;

// -------- persistent device state (no allocations allowed) --------
__device__ float gH0[2][8][BB][HH];   // [parity][slot][b][u] layer-0 hidden, ping-pong
__device__ float gH1[2][8][BB][HH];   // layer-1 hidden
__device__ unsigned g_barc = 0;       // final global barrier
__device__ volatile unsigned g_barg = 0;
__device__ unsigned g_gc[8];          // per-group barrier counters
__device__ volatile unsigned g_gg[8]; // per-group generations (monotonic across replays)
__device__ unsigned g_outcnt[NWIN];   // per-window completion counters (reset at kernel end)

// -------- helpers --------
__device__ __forceinline__ ull pack2(float x, float y) {
    ull r; asm("mov.b64 %0, {%1, %2};" : "=l"(r) : "f"(x), "f"(y)); return r;
}
__device__ __forceinline__ float2 unpack2(ull v) {
    float2 r; asm("mov.b64 {%0, %1}, %2;" : "=f"(r.x), "=f"(r.y) : "l"(v)); return r;
}
__device__ __forceinline__ void fma2(ull& d, ull a, ull b) {
    asm("fma.rn.f32x2 %0, %1, %2, %0;" : "+l"(d) : "l"(a), "l"(b));
}
__device__ __forceinline__ float sum2(ull v) { float2 f = unpack2(v); return f.x + f.y; }

// fast sigmoid / tanh: MUFU.EX2 + MUFU.RCP; rel err ~1e-6 (tolerance is 1e-3)
__device__ __forceinline__ float sigf(float x) {
    float e = __expf(-x);
    return __fdividef(1.0f, 1.0f + e);
}
__device__ __forceinline__ float tanhfast(float x) {
    float e = __expf(2.0f * x);
    return 1.0f - __fdividef(2.0f, e + 1.0f);
}

// 16-CTA group barrier (only CTAs sharing wg exchange h-state)
__device__ __forceinline__ void group_bar(int wg) {
    __threadfence();            // drain this CTA's global stores to L2
    __syncthreads();
    if (threadIdx.x == 0) {
        unsigned old = g_gg[wg];
        if (atomicAdd(&g_gc[wg], 1u) == 15u) {
            atomicExch(&g_gc[wg], 0u);
            __threadfence();
            g_gg[wg] = old + 1u;
        } else {
            unsigned spins = 0;
            while (g_gg[wg] == old && ++spins < SPIN_MAX) { }
            __threadfence();
        }
    }
    __syncthreads();
}

// final global barrier (used once, for replay-safe counter reset)
__device__ __forceinline__ void grid_bar_global() {
    __threadfence();
    __syncthreads();
    if (threadIdx.x == 0) {
        unsigned old = g_barg;
        if (atomicAdd(&g_barc, 1u) == NBLK - 1) {
            atomicExch(&g_barc, 0u);
            __threadfence();
            g_barg = old + 1u;
        } else {
            unsigned spins = 0;
            while (g_barg == old && ++spins < SPIN_MAX) __nanosleep(32);
            __threadfence();
        }
    }
    __syncthreads();
}

// ---- quarter-chunk GEMM (K=32 of a staged 128-chunk). sH: [32][128] row-major. ----
__device__ __forceinline__ void gemm32(ull acc[4][4],
                                       const float* __restrict__ sH,
                                       const float* __restrict__ sW,
                                       int ul, int b0, int kh)
{
    const float* hp = sH + b0 * 128 + kh * 32;
    const float* wp = sW + kh * 2048 + ul * 4;
#pragma unroll
    for (int q = 0; q < 8; ++q) {
        ulonglong2 h0 = *(const ulonglong2*)(hp + 0 * 128 + q * 4);
        ulonglong2 h1 = *(const ulonglong2*)(hp + 1 * 128 + q * 4);
        ulonglong2 h2 = *(const ulonglong2*)(hp + 2 * 128 + q * 4);
        ulonglong2 h3 = *(const ulonglong2*)(hp + 3 * 128 + q * 4);
        {
            const float* w = wp + (2 * q) * 128;
            ulonglong2 wA = *(const ulonglong2*)(w);
            ulonglong2 wB = *(const ulonglong2*)(w + 64);
            fma2(acc[0][0], h0.x, wA.x); fma2(acc[0][1], h1.x, wA.x);
            fma2(acc[0][2], h2.x, wA.x); fma2(acc[0][3], h3.x, wA.x);
            fma2(acc[1][0], h0.x, wA.y); fma2(acc[1][1], h1.x, wA.y);
            fma2(acc[1][2], h2.x, wA.y); fma2(acc[1][3], h3.x, wA.y);
            fma2(acc[2][0], h0.x, wB.x); fma2(acc[2][1], h1.x, wB.x);
            fma2(acc[2][2], h2.x, wB.x); fma2(acc[2][3], h3.x, wB.x);
            fma2(acc[3][0], h0.x, wB.y); fma2(acc[3][1], h1.x, wB.y);
            fma2(acc[3][2], h2.x, wB.y); fma2(acc[3][3], h3.x, wB.y);
        }
        {
            const float* w = wp + (2 * q + 1) * 128;
            ulonglong2 wA = *(const ulonglong2*)(w);
            ulonglong2 wB = *(const ulonglong2*)(w + 64);
            fma2(acc[0][0], h0.y, wA.x); fma2(acc[0][1], h1.y, wA.x);
            fma2(acc[0][2], h2.y, wA.x); fma2(acc[0][3], h3.y, wA.x);
            fma2(acc[1][0], h0.y, wA.y); fma2(acc[1][1], h1.y, wA.y);
            fma2(acc[1][2], h2.y, wA.y); fma2(acc[1][3], h3.y, wA.y);
            fma2(acc[2][0], h0.y, wB.x); fma2(acc[2][1], h1.y, wB.x);
            fma2(acc[2][2], h2.y, wB.x); fma2(acc[2][3], h3.y, wB.x);
            fma2(acc[3][0], h0.y, wB.y); fma2(acc[3][1], h1.y, wB.y);
            fma2(acc[3][2], h2.y, wB.y); fma2(acc[3][3], h3.y, wB.y);
        }
    }
}

// K=16 x-part GEMM over sX [32][16] (kh==0 warps only)
__device__ __forceinline__ void gemm16(ull acc[4][4],
                                       const float* __restrict__ sX,
                                       const float* __restrict__ sW,
                                       int ul, int b0)
{
    const float* hp = sX + b0 * 16;
    const float* wp = sW + ul * 4;
#pragma unroll
    for (int q = 0; q < 4; ++q) {
        ulonglong2 h0 = *(const ulonglong2*)(hp + 0 * 16 + q * 4);
        ulonglong2 h1 = *(const ulonglong2*)(hp + 1 * 16 + q * 4);
        ulonglong2 h2 = *(const ulonglong2*)(hp + 2 * 16 + q * 4);
        ulonglong2 h3 = *(const ulonglong2*)(hp + 3 * 16 + q * 4);
#pragma unroll
        for (int e = 0; e < 2; ++e) {
            const float* w = wp + (2 * q + e) * 128;
            ulonglong2 wA = *(const ulonglong2*)(w);
            ulonglong2 wB = *(const ulonglong2*)(w + 64);
            ull v0 = e ? h0.y : h0.x, v1 = e ? h1.y : h1.x;
            ull v2 = e ? h2.y : h2.x, v3 = e ? h3.y : h3.x;
            fma2(acc[0][0], v0, wA.x); fma2(acc[0][1], v1, wA.x);
            fma2(acc[0][2], v2, wA.x); fma2(acc[0][3], v3, wA.x);
            fma2(acc[1][0], v0, wA.y); fma2(acc[1][1], v1, wA.y);
            fma2(acc[1][2], v2, wA.y); fma2(acc[1][3], v3, wA.y);
            fma2(acc[2][0], v0, wB.x); fma2(acc[2][1], v1, wB.x);
            fma2(acc[2][2], v2, wB.x); fma2(acc[2][3], v3, wB.x);
            fma2(acc[3][0], v0, wB.y); fma2(acc[3][1], v1, wB.y);
            fma2(acc[3][2], v2, wB.y); fma2(acc[3][3], v3, wB.y);
        }
    }
}

__device__ __forceinline__ void ldg_chunk(float4 r[2], const float* __restrict__ src, int tid) {
#pragma unroll
    for (int j = 0; j < 2; ++j) {
        int idx = tid + j * NTHR;
        int b = idx >> 5, q = idx & 31;
        r[j] = __ldcg((const float4*)(src + b * HH) + q);
    }
}
__device__ __forceinline__ void sts_chunk(const float4 r[2], float* __restrict__ sH, int tid) {
#pragma unroll
    for (int j = 0; j < 2; ++j) {
        int idx = tid + j * NTHR;
        *(float4*)(sH + idx * 4) = r[j];
    }
}

__device__ __forceinline__ void stage_w256(const float* __restrict__ src,
                                           float* __restrict__ dst,
                                           int ubase, int tid)
{
    for (int i = tid; i < 8192; i += NTHR) {
        int r = i >> 7, k2 = i & 127;
        int uu = r >> 2, g = r & 3;
        int grow = g * 256 + ubase + uu;
        float2 w = __ldg((const float2*)(src + grow * 256 + 2 * k2));
        int doff = k2 * 128 + (g >> 1) * 64 + uu * 4 + (g & 1) * 2;
        dst[doff] = w.x; dst[doff + 1] = w.y;
    }
}

__global__ void __launch_bounds__(NTHR, 1)
orlstm_kernel(const float* __restrict__ traj,
              const float* __restrict__ Wih0, const float* __restrict__ Whh0,
              const float* __restrict__ bih0, const float* __restrict__ bhh0,
              const float* __restrict__ Wih1, const float* __restrict__ Whh1,
              const float* __restrict__ bih1, const float* __restrict__ bhh1,
              const float* __restrict__ Wlin, const float* __restrict__ blin,
              float* __restrict__ outp)
{
    extern __shared__ float smem[];
    float* sWhh0 = smem;                    // 16384 fl
    float* sWih1 = sWhh0 + 16384;
    float* sWhh1 = sWih1 + 16384;
    float* sWih0 = sWhh1 + 16384;           // 1024 fl
    float* sB0   = sWih0 + 1024;            // 64
    float* sB1   = sB0 + 64;                // 64
    float* sX    = sB1 + 64;                // 512
    float* sH    = sX + 512;                // 4096 fl (staging; fold buf kh=1,2)
    float* sF    = sH + 4096;               // 2048 fl (fold buf kh=3)
    // total 56960 floats = 227840 B

    const int tid   = threadIdx.x;
    const int us    = blockIdx.x & 15;      // unit-slice 0..15
    const int wg    = blockIdx.x >> 4;      // window slot 0..7
    const int ubase = us * 16;
    const int ul    = tid & 15;
    const int bq    = (tid >> 4) & 7;
    const int kh    = tid >> 7;
    const int t128  = tid & 127;
    const int b0    = bq * 4;
    const int u     = ubase + ul;

    // ---- one-time weight staging ----
    stage_w256(Whh0, sWhh0, ubase, tid);
    stage_w256(Wih1, sWih1, ubase, tid);
    stage_w256(Whh1, sWhh1, ubase, tid);
    for (int i = tid; i < 512; i += NTHR) {
        int r = i >> 3, k2 = i & 7;
        int uu = r >> 2, g = r & 3;
        int grow = g * 256 + ubase + uu;
        float2 w = __ldg((const float2*)(Wih0 + grow * 16 + 2 * k2));
        int doff = k2 * 128 + (g >> 1) * 64 + uu * 4 + (g & 1) * 2;
        sWih0[doff] = w.x; sWih0[doff + 1] = w.y;
    }
    if (tid < 64) {
        int uu = tid >> 2, g = tid & 3;
        int grow = g * 256 + ubase + uu;
        sB0[uu * 4 + g] = __ldg(bih0 + grow) + __ldg(bhh0 + grow);
        sB1[uu * 4 + g] = __ldg(bih1 + grow) + __ldg(bhh1 + grow);
    }
    __syncthreads();

    float c0s[4] = {0.f, 0.f, 0.f, 0.f};   // layer-0 cell state (kh==0 threads)
    float c1s[4] = {0.f, 0.f, 0.f, 0.f};   // layer-1 cell state (lagged window)

    volatile unsigned* vcnt = (volatile unsigned*)g_outcnt;

    for (int k = 0; k < NSTEPS; ++k) {
        const int p  = k & 1;
        const int sA = (k - wg) & 7;            // layer-0 step this phase
        const int t0 = k - sA;                  // its window
        const bool activeA = (t0 >= 0) && (t0 < NWIN);
        const int sB = (k - 1 - wg) & 7;        // layer-1 step (lags one phase)
        const int t1 = (k - 1) - sB;            // its window
        const bool activeB = (t1 >= 0) && (t1 < NWIN);

        ull acc[4][4];
        float hn1[4];

        // ================ LAYER 1 FIRST: h1(sB) for window t1 ================
        // x = h0(sB) = gH0[p] (last phase); recurrent = gH1[p]; writes gH1[p^1].
        // Runs BEFORE layer-0 so every out[] any layer-0 waits on this phase is
        // already produced (acyclic phase-level dependency graph; no deadlock).
        if (activeB) {
            if (kh == 0) {
#pragma unroll
                for (int g = 0; g < 4; ++g) {
                    ull bz = pack2(sB1[ul * 4 + g], 0.f);
#pragma unroll
                    for (int j = 0; j < 4; ++j) acc[g][j] = bz;
                }
            } else {
#pragma unroll
                for (int g = 0; g < 4; ++g)
#pragma unroll
                    for (int j = 0; j < 4; ++j) acc[g][j] = 0ull;
            }
            const float* srcX = &gH0[p][wg][0][0];   // h0(sB) from last phase
            const float* srcH = &gH1[p][wg][0][0];   // h1(sB-1) from last phase
            const int nch = (sB > 0) ? 4 : 2;
            float4 r[2];
            ldg_chunk(r, srcX, tid);
            for (int c = 0; c < nch; ++c) {
                __syncthreads();
                sts_chunk(r, sH, tid);
                __syncthreads();
                if (c + 1 < nch) {
                    const float* nsrc = (c + 1 < 2) ? (srcX + (c + 1) * 128)
                                                    : (srcH + (c - 1) * 128);
                    ldg_chunk(r, nsrc, tid);
                }
                const float* wb = (c < 2) ? (sWih1 + c * 8192)
                                          : (sWhh1 + (c - 2) * 8192);
                gemm32(acc, sH, wb, ul, b0, kh);
            }
            __syncthreads();
            if (kh == 1) {
#pragma unroll
                for (int g = 0; g < 4; ++g)
#pragma unroll
                    for (int j = 0; j < 4; ++j)
                        sH[(g * 4 + j) * 128 + t128] = sum2(acc[g][j]);
            } else if (kh == 2) {
#pragma unroll
                for (int g = 0; g < 4; ++g)
#pragma unroll
                    for (int j = 0; j < 4; ++j)
                        sH[2048 + (g * 4 + j) * 128 + t128] = sum2(acc[g][j]);
            } else if (kh == 3) {
#pragma unroll
                for (int g = 0; g < 4; ++g)
#pragma unroll
                    for (int j = 0; j < 4; ++j)
                        sF[(g * 4 + j) * 128 + t128] = sum2(acc[g][j]);
            }
            __syncthreads();

            if (kh == 0) {
                float* dstH = &gH1[p ^ 1][wg][0][0];
#pragma unroll
                for (int j = 0; j < 4; ++j) {
                    int b = b0 + j;
                    float gi = sum2(acc[0][j]) + sH[(0 * 4 + j) * 128 + t128] + sH[2048 + (0 * 4 + j) * 128 + t128] + sF[(0 * 4 + j) * 128 + t128];
                    float gf = sum2(acc[1][j]) + sH[(1 * 4 + j) * 128 + t128] + sH[2048 + (1 * 4 + j) * 128 + t128] + sF[(1 * 4 + j) * 128 + t128];
                    float gG = sum2(acc[2][j]) + sH[(2 * 4 + j) * 128 + t128] + sH[2048 + (2 * 4 + j) * 128 + t128] + sF[(2 * 4 + j) * 128 + t128];
                    float gO = sum2(acc[3][j]) + sH[(3 * 4 + j) * 128 + t128] + sH[2048 + (3 * 4 + j) * 128 + t128] + sF[(3 * 4 + j) * 128 + t128];
                    float cn = (sB ? sigf(gf) * c1s[j] : 0.f) + sigf(gi) * tanhfast(gG);
                    c1s[j] = cn;
                    float hn = sigf(gO) * tanhfast(cn);
                    hn1[j] = hn;
                    __stcg(dstH + b * HH + u, hn);
                    if (t1 == NWIN - 1 && sB == 7) {
                        outp[HN_OFF + BB * HH + b * HH + u] = hn;
                        outp[CN_OFF + BB * HH + b * HH + u] = cn;
                    }
                }
                if (sB == 7) {
                    float wl[8];
#pragma unroll
                    for (int o = 0; o < 8; ++o) wl[o] = __ldg(Wlin + o * HH + u);
#pragma unroll
                    for (int j = 0; j < 4; ++j) {
#pragma unroll
                        for (int o = 0; o < 8; ++o) {
                            float v = hn1[j] * wl[o];
                            v += __shfl_xor_sync(0xffffffffu, v, 1);
                            v += __shfl_xor_sync(0xffffffffu, v, 2);
                            v += __shfl_xor_sync(0xffffffffu, v, 4);
                            v += __shfl_xor_sync(0xffffffffu, v, 8);
                            if (ul == 0)
                                atomicAdd(outp + (b0 + j) * OUT_BS + t1 * OSZ + o, v);
                        }
                    }
                }
            }
            // finishing window: us==0 CTA adds the base (out[t1-1] + b_lin)
            if (sB == 7) {
                if (us == 0 && tid < 256) {
                    int b = tid >> 3, o = tid & 7;
                    float base;
                    if (t1 == 0) {
                        base = __ldg(traj + b * TRAJ_BS + 7 * DD + OSZ + o);
                    } else {
                        // produced at phase k-1 (window t1-1 finished then)
                        unsigned spins = 0;
                        while (vcnt[t1 - 1] < 16u && ++spins < SPIN_MAX) { }
                        __threadfence();
                        base = __ldcg(outp + b * OUT_BS + (t1 - 1) * OSZ + o);
                    }
                    atomicAdd(outp + b * OUT_BS + t1 * OSZ + o, base + __ldg(blin + o));
                }
                __threadfence();   // every thread: make its atomics visible first
                __syncthreads();
                if (tid == 0) {
                    atomicAdd(&g_outcnt[t1], 1u);   // release: this CTA's contributions done
                }
            }
        }

        // ================ LAYER 0: h0(sA) for window t0 ================
        // reads gH0[p] (h0(sA-1), written last phase); writes gH0[p^1]
        if (activeA) {
            if (sA == 0 && us == 0 && tid < 256) {
                int b = tid >> 3, o = tid & 7;
                __stcg(outp + b * OUT_BS + t0 * OSZ + o, 0.f);
            }
            {
                // out[jj] produced by some group's layer-1 THIS phase (already run
                // in-CTA; other groups' layer-1 has no same-phase waits -> progress)
                int jj = t0 + sA - 8;
                if (t0 >= 1 && jj >= 0 && tid == 0) {
                    unsigned spins = 0;
                    while (vcnt[jj] < 16u && ++spins < SPIN_MAX) { }
                    __threadfence();
                }
            }
            __syncthreads();

            // build x input [32][16]
            {
                int b = tid >> 4, col = tid & 15;
                float v;
                if (col < 8) {
                    int idx = (t0 >= 1 && t0 <= 7 && sA >= 8 - t0) ? (2 * t0 + sA - 1) : (t0 + sA);
                    v = __ldg(traj + b * TRAJ_BS + idx * DD + col);
                } else {
                    int j = t0 + sA - 8;
                    if (t0 >= 1 && j >= 0)
                        v = __ldcg(outp + b * OUT_BS + j * OSZ + (col - 8));
                    else
                        v = __ldg(traj + b * TRAJ_BS + (t0 + sA) * DD + col);
                }
                if (tid < 512) sX[tid] = v;
            }
            __syncthreads();

            if (kh == 0) {
#pragma unroll
                for (int g = 0; g < 4; ++g) {
                    ull bz = pack2(sB0[ul * 4 + g], 0.f);
#pragma unroll
                    for (int j = 0; j < 4; ++j) acc[g][j] = bz;
                }
                gemm16(acc, sX, sWih0, ul, b0);
            } else {
#pragma unroll
                for (int g = 0; g < 4; ++g)
#pragma unroll
                    for (int j = 0; j < 4; ++j) acc[g][j] = 0ull;
            }

            if (sA > 0) {
                const float* src = &gH0[p][wg][0][0];
                float4 r[2];
                ldg_chunk(r, src, tid);
#pragma unroll
                for (int c = 0; c < 2; ++c) {
                    __syncthreads();
                    sts_chunk(r, sH, tid);
                    __syncthreads();
                    if (c == 0) ldg_chunk(r, src + 128, tid);
                    gemm32(acc, sH, sWhh0 + c * 8192, ul, b0, kh);
                }
                __syncthreads();
                if (kh == 1) {
#pragma unroll
                    for (int g = 0; g < 4; ++g)
#pragma unroll
                        for (int j = 0; j < 4; ++j)
                            sH[(g * 4 + j) * 128 + t128] = sum2(acc[g][j]);
                } else if (kh == 2) {
#pragma unroll
                    for (int g = 0; g < 4; ++g)
#pragma unroll
                        for (int j = 0; j < 4; ++j)
                            sH[2048 + (g * 4 + j) * 128 + t128] = sum2(acc[g][j]);
                } else if (kh == 3) {
#pragma unroll
                    for (int g = 0; g < 4; ++g)
#pragma unroll
                        for (int j = 0; j < 4; ++j)
                            sF[(g * 4 + j) * 128 + t128] = sum2(acc[g][j]);
                }
                __syncthreads();
            }
            if (kh == 0) {
                float* dstH = &gH0[p ^ 1][wg][0][0];
#pragma unroll
                for (int j = 0; j < 4; ++j) {
                    int b = b0 + j;
                    float gi = sum2(acc[0][j]);
                    float gf = sum2(acc[1][j]);
                    float gG = sum2(acc[2][j]);
                    float gO = sum2(acc[3][j]);
                    if (sA > 0) {
                        gi += sH[(0 * 4 + j) * 128 + t128] + sH[2048 + (0 * 4 + j) * 128 + t128] + sF[(0 * 4 + j) * 128 + t128];
                        gf += sH[(1 * 4 + j) * 128 + t128] + sH[2048 + (1 * 4 + j) * 128 + t128] + sF[(1 * 4 + j) * 128 + t128];
                        gG += sH[(2 * 4 + j) * 128 + t128] + sH[2048 + (2 * 4 + j) * 128 + t128] + sF[(2 * 4 + j) * 128 + t128];
                        gO += sH[(3 * 4 + j) * 128 + t128] + sH[2048 + (3 * 4 + j) * 128 + t128] + sF[(3 * 4 + j) * 128 + t128];
                    }
                    float cn = (sA ? sigf(gf) * c0s[j] : 0.f) + sigf(gi) * tanhfast(gG);
                    c0s[j] = cn;
                    float hn = sigf(gO) * tanhfast(cn);
                    __stcg(dstH + b * HH + u, hn);
                    if (t0 == NWIN - 1 && sA == 7) {
                        outp[HN_OFF + b * HH + u] = hn;
                        outp[CN_OFF + b * HH + u] = cn;
                    }
                }
            }
        }

        group_bar(wg);   // single inter-CTA barrier per phase
    }

    // replay-safe reset of per-window counters
    grid_bar_global();
    if (blockIdx.x == 0) {
        for (int i = tid; i < NWIN; i += NTHR) g_outcnt[i] = 0u;
    }
}

extern "C" void kernel_launch(void* const* d_in, const int* in_sizes, int n_in,
                              void* d_out, int out_size)
{
    (void)in_sizes; (void)n_in; (void)out_size;
    const size_t smem_bytes = 56960 * sizeof(float);  // 227840 B
    cudaFuncSetAttribute(orlstm_kernel,
                         cudaFuncAttributeMaxDynamicSharedMemorySize,
                         (int)smem_bytes);
    orlstm_kernel<<<NBLK, NTHR, smem_bytes>>>(
        (const float*)d_in[0],
        (const float*)d_in[1], (const float*)d_in[2],
        (const float*)d_in[3], (const float*)d_in[4],
        (const float*)d_in[5], (const float*)d_in[6],
        (const float*)d_in[7], (const float*)d_in[8],
        (const float*)d_in[9], (const float*)d_in[10],
        (float*)d_out);
}